// round 1
// baseline (speedup 1.0000x reference)
#include <cuda_runtime.h>
#include <math.h>

// ---------------- constants ----------------
#define BB    8
#define SS    2048
#define NWRD  256
#define DM    768
#define HH    768
#define WLN   8
#define BN    2048        // BB*NWRD  (GRU batch == bert tokens)
#define TOK   16384       // BB*SS
#define NHEAD 4
#define DHD   192
#define FFD   3072
#define G3    2304        // 3*HH

// ---------------- scratch (device globals; no allocs allowed) ----------------
__device__ float g_seg[TOK * DM];               // 50 MB  token emb + pos
__device__ float g_y0[BN * WLN * 2 * HH];       // 100 MB layer0 bigru out (cat)
__device__ float g_y1[BN * WLN * 2 * HH];       // 100 MB layer1 bigru out (cat)
__device__ float g_ha[2 * BN * HH];             // gru hidden ping
__device__ float g_hb[2 * BN * HH];             // gru hidden pong
__device__ float g_xn[BN * DM];
__device__ float g_qkv[BN * G3];
__device__ float g_q [BB * NHEAD * NWRD * DHD];
__device__ float g_k [BB * NHEAD * NWRD * DHD];
__device__ float g_vt[BB * NHEAD * DHD * NWRD];
__device__ float g_s [BB * NHEAD * NWRD * NWRD];
__device__ float g_ob[BB * NHEAD * NWRD * DHD];
__device__ float g_oc[BN * DM];
__device__ float g_f1[BN * FFD];

__device__ __forceinline__ float sigmoidf_(float x) { return 1.0f / (1.0f + expf(-x)); }

// ---------------- embedding + sinusoid(pos within word) ----------------
__global__ void embed_kernel(const int* __restrict__ x, const float* __restrict__ emb) {
    int row = blockIdx.x;          // 0..TOK-1 flat token, == n*8+t
    int t   = row & (WLN - 1);
    int sym = x[row];
    for (int d = threadIdx.x; d < DM; d += blockDim.x) {
        int   e2  = (d >> 1) << 1;
        float ang = (float)t * powf(10000.0f, -(float)e2 / (float)DM);
        float pe  = (d & 1) ? cosf(ang) : sinf(ang);
        g_seg[(long long)row * DM + d] = emb[sym * DM + d] + pe;
    }
}

// ---------------- fused GRU step: gates = x_t@Wih^T + h@Whh^T, then gate math ----
// grid: (HH/64, BN/64, 2 dirs), block 256 (16x16, each thread 4x4 outputs)
#define GRU_PHASE(ABASE, LDA, WBASE, KW, ACCN)                                          \
    for (int kb = 0; kb < (KW); kb += 16) {                                             \
        float4 av = *(const float4*)((ABASE) + (long long)(m0 + lr) * (LDA) + kb + lc); \
        Xs[lc+0][lr]=av.x; Xs[lc+1][lr]=av.y; Xs[lc+2][lr]=av.z; Xs[lc+3][lr]=av.w;     \
        _Pragma("unroll")                                                               \
        for (int g = 0; g < 3; g++) {                                                   \
            float4 wv = *(const float4*)((WBASE) + (long long)(g*HH + j0 + lr) * (KW) + kb + lc); \
            Ws[g][lc+0][lr]=wv.x; Ws[g][lc+1][lr]=wv.y; Ws[g][lc+2][lr]=wv.z; Ws[g][lc+3][lr]=wv.w; \
        }                                                                               \
        __syncthreads();                                                                \
        _Pragma("unroll")                                                               \
        for (int kk = 0; kk < 16; kk++) {                                               \
            float4 a4 = *(const float4*)&Xs[kk][ty*4];                                  \
            float4 r4 = *(const float4*)&Ws[0][kk][tx*4];                               \
            float4 z4 = *(const float4*)&Ws[1][kk][tx*4];                               \
            float4 n4 = *(const float4*)&Ws[2][kk][tx*4];                               \
            float aa[4]={a4.x,a4.y,a4.z,a4.w};                                          \
            float rr[4]={r4.x,r4.y,r4.z,r4.w};                                          \
            float zz[4]={z4.x,z4.y,z4.z,z4.w};                                          \
            float nn[4]={n4.x,n4.y,n4.z,n4.w};                                          \
            _Pragma("unroll") for (int i=0;i<4;i++)                                     \
              _Pragma("unroll") for (int jj=0;jj<4;jj++) {                              \
                ar_[i][jj] = fmaf(aa[i], rr[jj], ar_[i][jj]);                           \
                az_[i][jj] = fmaf(aa[i], zz[jj], az_[i][jj]);                           \
                ACCN[i][jj] = fmaf(aa[i], nn[jj], ACCN[i][jj]);                         \
              }                                                                         \
        }                                                                               \
        __syncthreads();                                                                \
    }

__global__ __launch_bounds__(256)
void gru_step_kernel(const float* __restrict__ x, int ldx, int tsx, int Kx,
                     const float* __restrict__ wih, const float* __restrict__ whh,
                     const float* __restrict__ bih, const float* __restrict__ bhh,
                     const float* __restrict__ hprev, float* __restrict__ hnext,
                     float* __restrict__ y, int y_row, int y_t, int y_dir,
                     int step)
{
    int dir = blockIdx.z;
    int t = dir ? (WLN - 1 - step) : step;
    x     += (long long)t * tsx;
    wih   += (long long)dir * G3 * Kx;
    whh   += (long long)dir * G3 * HH;
    bih   += dir * G3;
    bhh   += dir * G3;
    hprev += (long long)dir * BN * HH;
    hnext += (long long)dir * BN * HH;
    y     += (long long)t * y_t + (long long)dir * y_dir;

    __shared__ float Xs[16][64];
    __shared__ float Ws[3][16][64];
    int tid = threadIdx.x;
    int tx = tid & 15, ty = tid >> 4;
    int m0 = blockIdx.y * 64, j0 = blockIdx.x * 64;
    int lr = tid >> 2, lc = (tid & 3) << 2;

    float ar_[4][4] = {};   // r gate (x+h combined)
    float az_[4][4] = {};   // z gate (x+h combined)
    float an_x[4][4] = {};  // n gate, x part (gi_n)
    float an_h[4][4] = {};  // n gate, h part (gh_n)

    GRU_PHASE(x,     ldx, wih, Kx, an_x);
    GRU_PHASE(hprev, HH,  whh, HH, an_h);

    #pragma unroll
    for (int i = 0; i < 4; i++) {
        int n_ = m0 + ty * 4 + i;
        #pragma unroll
        for (int jj = 0; jj < 4; jj++) {
            int j = j0 + tx * 4 + jj;
            float r  = sigmoidf_(ar_[i][jj] + bih[j]      + bhh[j]);
            float z  = sigmoidf_(az_[i][jj] + bih[HH + j] + bhh[HH + j]);
            float nn = tanhf(an_x[i][jj] + bih[2*HH + j] + r * (an_h[i][jj] + bhh[2*HH + j]));
            float hp = hprev[(long long)n_ * HH + j];
            float hv = (1.0f - z) * nn + z * hp;
            hnext[(long long)n_ * HH + j] = hv;
            y[(long long)n_ * y_row + j]  = hv;
        }
    }
}

// ---------------- word embedding pool + bert emb + sinusoid(word pos) ----------------
__global__ void word_embed_kernel(const float* __restrict__ bert_emb, float* __restrict__ out) {
    int n = blockIdx.x;            // 0..BN-1 ; (b,w) = (n/NWRD, n%NWRD)
    int w = n & (NWRD - 1);
    const float* y0p = &g_y1[(long long)(n * WLN + 0) * (2 * HH)];
    const float* y7p = &g_y1[(long long)(n * WLN + WLN - 1) * (2 * HH)];
    for (int d = threadIdx.x; d < DM; d += blockDim.x) {
        float we = y0p[d] + y7p[d] + y0p[HH + d] + y7p[HH + d];
        int   e2  = (d >> 1) << 1;
        float ang = (float)w * powf(10000.0f, -(float)e2 / (float)DM);
        float pe  = (d & 1) ? cosf(ang) : sinf(ang);
        out[(long long)n * DM + d] = we + bert_emb[(long long)n * DM + d] + pe;
    }
}

// ---------------- generic tiled GEMM: C[m,n] = sum_k A[m,k]*W[n,k] (+bias) ----------
// EPI: 0 = store, 1 = gelu(tanh) store, 2 = add to existing C (residual)
template<int EPI>
__global__ __launch_bounds__(256)
void gemm_tn(const float* __restrict__ A, const float* __restrict__ W,
             const float* __restrict__ bias, float* __restrict__ C,
             int N, int K, long long sA, long long sW, long long sC)
{
    A += (long long)blockIdx.z * sA;
    W += (long long)blockIdx.z * sW;
    C += (long long)blockIdx.z * sC;
    __shared__ float As[16][64];
    __shared__ float Bs[16][64];
    int tid = threadIdx.x;
    int tx = tid & 15, ty = tid >> 4;
    int m0 = blockIdx.y * 64, n0 = blockIdx.x * 64;
    int lr = tid >> 2, lc = (tid & 3) << 2;
    float acc[4][4] = {};
    const float* Ap = A + (long long)(m0 + lr) * K + lc;
    const float* Wp = W + (long long)(n0 + lr) * K + lc;
    for (int kb = 0; kb < K; kb += 16) {
        float4 av = *(const float4*)(Ap + kb);
        float4 wv = *(const float4*)(Wp + kb);
        As[lc+0][lr]=av.x; As[lc+1][lr]=av.y; As[lc+2][lr]=av.z; As[lc+3][lr]=av.w;
        Bs[lc+0][lr]=wv.x; Bs[lc+1][lr]=wv.y; Bs[lc+2][lr]=wv.z; Bs[lc+3][lr]=wv.w;
        __syncthreads();
        #pragma unroll
        for (int kk = 0; kk < 16; kk++) {
            float4 a4 = *(const float4*)&As[kk][ty*4];
            float4 b4 = *(const float4*)&Bs[kk][tx*4];
            float aa[4]={a4.x,a4.y,a4.z,a4.w};
            float bb[4]={b4.x,b4.y,b4.z,b4.w};
            #pragma unroll
            for (int i=0;i<4;i++)
              #pragma unroll
              for (int j=0;j<4;j++)
                acc[i][j] = fmaf(aa[i], bb[j], acc[i][j]);
        }
        __syncthreads();
    }
    #pragma unroll
    for (int i = 0; i < 4; i++) {
        int row = m0 + ty * 4 + i;
        #pragma unroll
        for (int j = 0; j < 4; j++) {
            int col = n0 + tx * 4 + j;
            float v = acc[i][j];
            if (bias) v += bias[col];
            float* cp = &C[(long long)row * N + col];
            if (EPI == 1) {
                float u = v;
                float c = 0.7978845608028654f * (u + 0.044715f * u * u * u);
                v = 0.5f * u * (1.0f + tanhf(c));
            }
            if (EPI == 2) v += *cp;
            *cp = v;
        }
    }
}

// ---------------- layernorm (row=2048, D=768), 256 threads x 3 elems ----------------
__global__ void layernorm_kernel(const float* __restrict__ in, const float* __restrict__ g,
                                 const float* __restrict__ b, float* __restrict__ out)
{
    __shared__ float red[256];
    int row = blockIdx.x, tid = threadIdx.x;
    const float* p = in + (long long)row * DM;
    float x0 = p[tid], x1 = p[tid + 256], x2 = p[tid + 512];
    red[tid] = x0 + x1 + x2;
    __syncthreads();
    for (int o = 128; o; o >>= 1) { if (tid < o) red[tid] += red[tid + o]; __syncthreads(); }
    float mean = red[0] * (1.0f / DM);
    __syncthreads();
    float d0 = x0 - mean, d1 = x1 - mean, d2 = x2 - mean;
    red[tid] = d0 * d0 + d1 * d1 + d2 * d2;
    __syncthreads();
    for (int o = 128; o; o >>= 1) { if (tid < o) red[tid] += red[tid + o]; __syncthreads(); }
    float rs = rsqrtf(red[0] * (1.0f / DM) + 1e-6f);
    float* q = out + (long long)row * DM;
    q[tid]       = d0 * rs * g[tid]       + b[tid];
    q[tid + 256] = d1 * rs * g[tid + 256] + b[tid + 256];
    q[tid + 512] = d2 * rs * g[tid + 512] + b[tid + 512];
}

// ---------------- qkv reshape: [tok,2304] -> Q/K [bh,q,d], Vt [bh,d,q] -------------
__global__ void qkv_reshape_kernel() {
    long long idx = (long long)blockIdx.x * 256 + threadIdx.x;   // over BN*DM
    int tok = (int)(idx / DM), c = (int)(idx % DM);
    int h = c / DHD, d = c % DHD;
    int b = tok / NWRD, q = tok % NWRD;
    long long base = (long long)tok * G3;
    float qv = g_qkv[base + c];
    float kv = g_qkv[base + DM + c];
    float vv = g_qkv[base + 2 * DM + c];
    long long bh = b * NHEAD + h;
    g_q [bh * NWRD * DHD + (long long)q * DHD + d] = qv;
    g_k [bh * NWRD * DHD + (long long)q * DHD + d] = kv;
    g_vt[bh * DHD * NWRD + (long long)d * NWRD + q] = vv;
}

// ---------------- softmax over rows of 256 with 1/sqrt(192) scale ------------------
__global__ void softmax_kernel() {
    __shared__ float red[256];
    int row = blockIdx.x, tid = threadIdx.x;
    float* p = g_s + (long long)row * NWRD;
    float v = p[tid] * 0.07216878364870323f;
    red[tid] = v;
    __syncthreads();
    for (int o = 128; o; o >>= 1) { if (tid < o) red[tid] = fmaxf(red[tid], red[tid + o]); __syncthreads(); }
    float mx = red[0];
    __syncthreads();
    float e = expf(v - mx);
    red[tid] = e;
    __syncthreads();
    for (int o = 128; o; o >>= 1) { if (tid < o) red[tid] += red[tid + o]; __syncthreads(); }
    p[tid] = e / red[0];
}

// ---------------- attention out reshape: [bh,q,d] -> [tok, h*192+d] ----------------
__global__ void o_reshape_kernel() {
    long long idx = (long long)blockIdx.x * 256 + threadIdx.x;   // over BN*DM
    int tok = (int)(idx / DM), c = (int)(idx % DM);
    int h = c / DHD, d = c % DHD;
    int b = tok / NWRD, q = tok % NWRD;
    g_oc[idx] = g_ob[(((long long)(b * NHEAD + h)) * NWRD + q) * DHD + d];
}

// ---------------- launch ----------------
extern "C" void kernel_launch(void* const* d_in, const int* in_sizes, int n_in,
                              void* d_out, int out_size)
{
    const int*   x        = (const int*)  d_in[0];
    // d_in[1] = gate_for_words (uniform segmentation; unused)
    const float* bert_emb = (const float*)d_in[2];
    const float* emb      = (const float*)d_in[3];
    const float* wih0     = (const float*)d_in[4];
    const float* whh0     = (const float*)d_in[5];
    const float* bih0     = (const float*)d_in[6];
    const float* bhh0     = (const float*)d_in[7];
    const float* wih1     = (const float*)d_in[8];
    const float* whh1     = (const float*)d_in[9];
    const float* bih1     = (const float*)d_in[10];
    const float* bhh1     = (const float*)d_in[11];
    const float* wqkv     = (const float*)d_in[12];
    const float* bqkv     = (const float*)d_in[13];
    const float* wo       = (const float*)d_in[14];
    const float* bo       = (const float*)d_in[15];
    const float* w1       = (const float*)d_in[16];
    const float* b1       = (const float*)d_in[17];
    const float* w2       = (const float*)d_in[18];
    const float* b2       = (const float*)d_in[19];
    const float* ln1g     = (const float*)d_in[20];
    const float* ln1b     = (const float*)d_in[21];
    const float* ln2g     = (const float*)d_in[22];
    const float* ln2b     = (const float*)d_in[23];
    float* hout = (float*)d_out;

    float *seg, *y0, *y1, *ha, *hb, *xn, *qkv, *q, *k, *vt, *s, *ob, *oc, *f1;
    cudaGetSymbolAddress((void**)&seg, g_seg);
    cudaGetSymbolAddress((void**)&y0,  g_y0);
    cudaGetSymbolAddress((void**)&y1,  g_y1);
    cudaGetSymbolAddress((void**)&ha,  g_ha);
    cudaGetSymbolAddress((void**)&hb,  g_hb);
    cudaGetSymbolAddress((void**)&xn,  g_xn);
    cudaGetSymbolAddress((void**)&qkv, g_qkv);
    cudaGetSymbolAddress((void**)&q,   g_q);
    cudaGetSymbolAddress((void**)&k,   g_k);
    cudaGetSymbolAddress((void**)&vt,  g_vt);
    cudaGetSymbolAddress((void**)&s,   g_s);
    cudaGetSymbolAddress((void**)&ob,  g_ob);
    cudaGetSymbolAddress((void**)&oc,  g_oc);
    cudaGetSymbolAddress((void**)&f1,  g_f1);

    // 1. token embedding + intra-word position
    embed_kernel<<<TOK, 256>>>(x, emb);

    // 2. BiGRU layer 0 (fused x@Wih + h@Whh per step; both dirs via blockIdx.z)
    cudaMemsetAsync(ha, 0, (size_t)2 * BN * HH * sizeof(float));
    for (int st = 0; st < WLN; st++) {
        const float* hp = (st & 1) ? hb : ha;
        float*       hn = (st & 1) ? ha : hb;
        gru_step_kernel<<<dim3(HH/64, BN/64, 2), 256>>>(
            seg, WLN * DM, DM, DM, wih0, whh0, bih0, bhh0,
            hp, hn, y0, WLN * 2 * HH, 2 * HH, HH, st);
    }

    // 3. BiGRU layer 1 (input = concat 1536)
    cudaMemsetAsync(ha, 0, (size_t)2 * BN * HH * sizeof(float));
    for (int st = 0; st < WLN; st++) {
        const float* hp = (st & 1) ? hb : ha;
        float*       hn = (st & 1) ? ha : hb;
        gru_step_kernel<<<dim3(HH/64, BN/64, 2), 256>>>(
            y0, WLN * 2 * HH, 2 * HH, 2 * HH, wih1, whh1, bih1, bhh1,
            hp, hn, y1, WLN * 2 * HH, 2 * HH, HH, st);
    }

    // 4. word pooling + bert embeddings + word-position sinusoid -> h (in d_out)
    word_embed_kernel<<<BN, 256>>>(bert_emb, hout);

    // 5. 3 pre-norm transformer layers
    for (int l = 0; l < 3; l++) {
        layernorm_kernel<<<BN, 256>>>(hout, ln1g + l * DM, ln1b + l * DM, xn);
        gemm_tn<0><<<dim3(G3/64, BN/64, 1), 256>>>(
            xn, wqkv + (long long)l * 3 * DM * DM, bqkv + l * 3 * DM, qkv, G3, DM, 0, 0, 0);
        qkv_reshape_kernel<<<(BN * DM) / 256, 256>>>();
        // scores: S = Q @ K^T  (32 batches of 256x256x192)
        gemm_tn<0><<<dim3(NWRD/64, NWRD/64, BB * NHEAD), 256>>>(
            q, k, nullptr, s, NWRD, DHD,
            (long long)NWRD * DHD, (long long)NWRD * DHD, (long long)NWRD * NWRD);
        softmax_kernel<<<BB * NHEAD * NWRD, 256>>>();
        // O = S @ V  (V pre-transposed: C[q,d] = sum_k S[q,k] * Vt[d,k])
        gemm_tn<0><<<dim3(DHD/64, NWRD/64, BB * NHEAD), 256>>>(
            s, vt, nullptr, ob, DHD, NWRD,
            (long long)NWRD * NWRD, (long long)DHD * NWRD, (long long)NWRD * DHD);
        o_reshape_kernel<<<(BN * DM) / 256, 256>>>();
        // h += O @ Wo^T + bo
        gemm_tn<2><<<dim3(DM/64, BN/64, 1), 256>>>(
            oc, wo + (long long)l * DM * DM, bo + l * DM, hout, DM, DM, 0, 0, 0);
        layernorm_kernel<<<BN, 256>>>(hout, ln2g + l * DM, ln2b + l * DM, xn);
        // f1 = gelu(xn @ W1^T + b1)
        gemm_tn<1><<<dim3(FFD/64, BN/64, 1), 256>>>(
            xn, w1 + (long long)l * FFD * DM, b1 + l * FFD, f1, FFD, DM, 0, 0, 0);
        // h += f1 @ W2^T + b2
        gemm_tn<2><<<dim3(DM/64, BN/64, 1), 256>>>(
            f1, w2 + (long long)l * DM * FFD, b2 + l * DM, hout, DM, FFD, 0, 0, 0);
    }
}

// round 4
// speedup vs baseline: 3.2037x; 3.2037x over previous
#include <cuda_runtime.h>
#include <math.h>
#include <stdint.h>

// ---------------- constants ----------------
#define BB    8
#define NWRD  256
#define DM    768
#define HH    768
#define WLN   8
#define BN    2048        // BB*NWRD
#define TOK   16384       // BB*S
#define NHEAD 4
#define DHD   192
#define FFD   3072
#define G3    2304        // 3*HH

// ---------------- one arena, reuse-aware (556 MB total) ----------------
// GI   : input gates (layer0 then layer1 reuse)      75,497,472 floats
// Y    : y0 (layer0 out) then y1 (layer1 out) reuse  25,165,824
// SEGB : seg (token emb) then all BERT scratch       22,544,384
// GH   : per-step hidden gates                        9,437,184
// HA/HB: hidden ping-pong                             3,145,728 each
#define OFF_GI   0LL
#define OFF_Y    75497472LL
#define OFF_SEGB 100663296LL
#define OFF_GH   123207680LL
#define OFF_HA   132644864LL
#define OFF_HB   135790592LL
#define ARENA_FLOATS 138936320LL
// BERT sub-offsets within SEGB (seg itself also starts at SEGB+0)
#define SB_XN   0LL
#define SB_QKV  1572864LL
#define SB_Q    6291456LL
#define SB_K    7864320LL
#define SB_VT   9437184LL
#define SB_S    11010048LL
#define SB_OB   13107200LL
#define SB_OC   14680064LL
#define SB_F1   16252928LL

__device__ __align__(16) float g_arena[ARENA_FLOATS];
__device__ float g_pow[DM];

__device__ __forceinline__ float sigmoidf_(float x) { return 1.0f / (1.0f + expf(-x)); }

__device__ __forceinline__ uint32_t f2tf(float f) {
    uint32_t r; asm("cvt.rna.tf32.f32 %0, %1;" : "=r"(r) : "f"(f)); return r;
}

#define MMA8(d, a, b)                                                        \
    asm volatile("mma.sync.aligned.m16n8k8.row.col.f32.tf32.tf32.f32 "       \
        "{%0,%1,%2,%3},{%4,%5,%6,%7},{%8,%9},{%0,%1,%2,%3};"                 \
        : "+f"(d[0]), "+f"(d[1]), "+f"(d[2]), "+f"(d[3])                     \
        : "r"(a[0]), "r"(a[1]), "r"(a[2]), "r"(a[3]), "r"(b[0]), "r"(b[1]))

// ---------------- sinusoid freq table ----------------
__global__ void init_pow_kernel() {
    int d = threadIdx.x;
    int e2 = (d >> 1) << 1;
    g_pow[d] = powf(10000.0f, -(float)e2 / (float)DM);
}

// ---------------- embedding + sinusoid(pos within word) ----------------
__global__ void embed_kernel(const int* __restrict__ x, const float* __restrict__ emb,
                             float* __restrict__ seg) {
    int row = blockIdx.x;
    int t   = row & (WLN - 1);
    int sym = x[row];
    for (int d = threadIdx.x; d < DM; d += blockDim.x) {
        float ang = (float)t * g_pow[d];
        float pe  = (d & 1) ? cosf(ang) : sinf(ang);
        seg[(long long)row * DM + d] = emb[sym * DM + d] + pe;
    }
}

// ---------------- tf32 tensor-core GEMM: C[m,n] = A[m,k] @ W[n,k]^T (+bias, epi) ----
// 128x128x16 tiles, 256 threads (8 warps as 2x4, warp tile 64x32), cp.async 2-stage
// EPI: 0 plain, 1 gelu, 2 residual add.  NGUARD: bounds-check N dim (for N=192).
template<int EPI, int NGUARD>
__global__ __launch_bounds__(256, 1)
void gemm_tc(const float* __restrict__ A, const float* __restrict__ W,
             const float* __restrict__ bias, float* __restrict__ C,
             int M, int N, int K, long long sA, long long sW, long long sC)
{
    A += (long long)blockIdx.z * sA;
    W += (long long)blockIdx.z * sW;
    C += (long long)blockIdx.z * sC;
    __shared__ float As[2][128][20];
    __shared__ float Bs[2][128][20];
    const int tid  = threadIdx.x;
    const int lane = tid & 31, warp = tid >> 5;
    const int wm = (warp >> 2) * 64;
    const int wn = (warp & 3) * 32;
    const int m0 = blockIdx.y * 128, n0 = blockIdx.x * 128;

    const int r0 = tid >> 2, kg = (tid & 3) << 2;   // r0: 0..63
    const int r1 = r0 + 64;

    const float* Ap0 = A + (long long)(m0 + r0) * K + kg;
    const float* Ap1 = A + (long long)(m0 + r1) * K + kg;
    const float* Wp0 = W + (long long)(n0 + r0) * K + kg;
    const float* Wp1 = W + (long long)(n0 + r1) * K + kg;
    int bok0 = 16, bok1 = 16;
    if (NGUARD) {
        if (n0 + r0 >= N) { bok0 = 0; Wp0 = W; }
        if (n0 + r1 >= N) { bok1 = 0; Wp1 = W; }
    }
    uint32_t sa0[2], sa1[2], sb0[2], sb1[2];
    #pragma unroll
    for (int b = 0; b < 2; b++) {
        sa0[b] = (uint32_t)__cvta_generic_to_shared(&As[b][r0][kg]);
        sa1[b] = (uint32_t)__cvta_generic_to_shared(&As[b][r1][kg]);
        sb0[b] = (uint32_t)__cvta_generic_to_shared(&Bs[b][r0][kg]);
        sb1[b] = (uint32_t)__cvta_generic_to_shared(&Bs[b][r1][kg]);
    }

#define LOADTILE(buf, kb) do {                                                             \
    asm volatile("cp.async.ca.shared.global [%0],[%1],16;" :: "r"(sa0[buf]), "l"(Ap0 + (kb))); \
    asm volatile("cp.async.ca.shared.global [%0],[%1],16;" :: "r"(sa1[buf]), "l"(Ap1 + (kb))); \
    asm volatile("cp.async.ca.shared.global [%0],[%1],16,%2;" :: "r"(sb0[buf]), "l"(Wp0 + (kb)), "r"(bok0)); \
    asm volatile("cp.async.ca.shared.global [%0],[%1],16,%2;" :: "r"(sb1[buf]), "l"(Wp1 + (kb)), "r"(bok1)); \
    asm volatile("cp.async.commit_group;"); } while (0)

    float acc[4][4][4] = {};
    const int KT = K >> 4;

    LOADTILE(0, 0);
    for (int it = 0; it < KT; it++) {
        const int cur = it & 1;
        if (it + 1 < KT) {
            LOADTILE(cur ^ 1, (it + 1) * 16);
            asm volatile("cp.async.wait_group 1;");
        } else {
            asm volatile("cp.async.wait_group 0;");
        }
        __syncthreads();
        #pragma unroll
        for (int kk = 0; kk < 2; kk++) {
            const int k0 = kk * 8 + (lane & 3);
            const int qr = lane >> 2;
            uint32_t a[4][4], b[4][2];
            #pragma unroll
            for (int i = 0; i < 4; i++) {
                int mr = wm + i * 16 + qr;
                a[i][0] = f2tf(As[cur][mr    ][k0]);
                a[i][1] = f2tf(As[cur][mr + 8][k0]);
                a[i][2] = f2tf(As[cur][mr    ][k0 + 4]);
                a[i][3] = f2tf(As[cur][mr + 8][k0 + 4]);
            }
            #pragma unroll
            for (int j = 0; j < 4; j++) {
                int nr = wn + j * 8 + qr;
                b[j][0] = f2tf(Bs[cur][nr][k0]);
                b[j][1] = f2tf(Bs[cur][nr][k0 + 4]);
            }
            #pragma unroll
            for (int i = 0; i < 4; i++)
                #pragma unroll
                for (int j = 0; j < 4; j++)
                    MMA8(acc[i][j], a[i], b[j]);
        }
        __syncthreads();
    }
#undef LOADTILE

    // epilogue
    #pragma unroll
    for (int i = 0; i < 4; i++) {
        int rowb = m0 + wm + i * 16 + (lane >> 2);
        #pragma unroll
        for (int rr = 0; rr < 2; rr++) {
            int r = rowb + rr * 8;
            #pragma unroll
            for (int j = 0; j < 4; j++) {
                int col = n0 + wn + j * 8 + (lane & 3) * 2;
                if (NGUARD && col >= N) continue;
                float v0 = acc[i][j][rr * 2 + 0];
                float v1 = acc[i][j][rr * 2 + 1];
                if (bias) { v0 += bias[col]; v1 += bias[col + 1]; }
                if (EPI == 1) {
                    float c0 = 0.7978845608028654f * (v0 + 0.044715f * v0 * v0 * v0);
                    float c1 = 0.7978845608028654f * (v1 + 0.044715f * v1 * v1 * v1);
                    v0 = 0.5f * v0 * (1.0f + tanhf(c0));
                    v1 = 0.5f * v1 * (1.0f + tanhf(c1));
                }
                float2* cp = (float2*)&C[(long long)r * N + col];
                if (EPI == 2) { float2 old = *cp; v0 += old.x; v1 += old.y; }
                *cp = make_float2(v0, v1);
            }
        }
    }
}

// ---------------- GRU gate elementwise (reads gi + gh, writes hnext + y) -----------
__global__ void gru_gate_kernel(const float* __restrict__ gi, const float* __restrict__ gh,
                                const float* __restrict__ bih, const float* __restrict__ bhh,
                                const float* __restrict__ hprev, float* __restrict__ hnext,
                                float* __restrict__ y, int step)
{
    int idx = blockIdx.x * blockDim.x + threadIdx.x;   // over 2*BN*HH/4
    const int JW = HH / 4;
    int j  = (idx % JW) * 4;
    int n  = (idx / JW) % BN;
    int dir = idx / (BN * JW);
    int t = dir ? (WLN - 1 - step) : step;
    long long tok = (long long)n * WLN + t;

    long long gib = ((long long)dir * TOK + tok) * G3;
    long long ghb = ((long long)dir * BN + n) * G3;
    const float4 gir = *(const float4*)(gi + gib + j);
    const float4 giz = *(const float4*)(gi + gib + HH + j);
    const float4 gin = *(const float4*)(gi + gib + 2 * HH + j);
    const float4 ghr = *(const float4*)(gh + ghb + j);
    const float4 ghz = *(const float4*)(gh + ghb + HH + j);
    const float4 ghn = *(const float4*)(gh + ghb + 2 * HH + j);
    const float4 bir = *(const float4*)(bih + dir * G3 + j);
    const float4 biz = *(const float4*)(bih + dir * G3 + HH + j);
    const float4 bin_ = *(const float4*)(bih + dir * G3 + 2 * HH + j);
    const float4 bhr = *(const float4*)(bhh + dir * G3 + j);
    const float4 bhz = *(const float4*)(bhh + dir * G3 + HH + j);
    const float4 bhn = *(const float4*)(bhh + dir * G3 + 2 * HH + j);
    long long hb = ((long long)dir * BN + n) * HH + j;
    const float4 hp = *(const float4*)(hprev + hb);

    float4 out;
    {
        float r = sigmoidf_(gir.x + bir.x + ghr.x + bhr.x);
        float z = sigmoidf_(giz.x + biz.x + ghz.x + bhz.x);
        float nn = tanhf(gin.x + bin_.x + r * (ghn.x + bhn.x));
        out.x = (1.0f - z) * nn + z * hp.x;
    }
    {
        float r = sigmoidf_(gir.y + bir.y + ghr.y + bhr.y);
        float z = sigmoidf_(giz.y + biz.y + ghz.y + bhz.y);
        float nn = tanhf(gin.y + bin_.y + r * (ghn.y + bhn.y));
        out.y = (1.0f - z) * nn + z * hp.y;
    }
    {
        float r = sigmoidf_(gir.z + bir.z + ghr.z + bhr.z);
        float z = sigmoidf_(giz.z + biz.z + ghz.z + bhz.z);
        float nn = tanhf(gin.z + bin_.z + r * (ghn.z + bhn.z));
        out.z = (1.0f - z) * nn + z * hp.z;
    }
    {
        float r = sigmoidf_(gir.w + bir.w + ghr.w + bhr.w);
        float z = sigmoidf_(giz.w + biz.w + ghz.w + bhz.w);
        float nn = tanhf(gin.w + bin_.w + r * (ghn.w + bhn.w));
        out.w = (1.0f - z) * nn + z * hp.w;
    }
    *(float4*)(hnext + hb) = out;
    *(float4*)(y + tok * (2 * HH) + (long long)dir * HH + j) = out;
}

// ---------------- word pooling + bert emb + sinusoid(word pos) ----------------
__global__ void word_embed_kernel(const float* __restrict__ y1,
                                  const float* __restrict__ bert_emb,
                                  float* __restrict__ out) {
    int n = blockIdx.x;
    int w = n & (NWRD - 1);
    const float* y0p = &y1[(long long)(n * WLN + 0) * (2 * HH)];
    const float* y7p = &y1[(long long)(n * WLN + WLN - 1) * (2 * HH)];
    for (int d = threadIdx.x; d < DM; d += blockDim.x) {
        float we = y0p[d] + y7p[d] + y0p[HH + d] + y7p[HH + d];
        float ang = (float)w * g_pow[d];
        float pe  = (d & 1) ? cosf(ang) : sinf(ang);
        out[(long long)n * DM + d] = we + bert_emb[(long long)n * DM + d] + pe;
    }
}

// ---------------- layernorm ----------------
__global__ void layernorm_kernel(const float* __restrict__ in, const float* __restrict__ g,
                                 const float* __restrict__ b, float* __restrict__ out)
{
    __shared__ float red[256];
    int row = blockIdx.x, tid = threadIdx.x;
    const float* p = in + (long long)row * DM;
    float x0 = p[tid], x1 = p[tid + 256], x2 = p[tid + 512];
    red[tid] = x0 + x1 + x2;
    __syncthreads();
    for (int o = 128; o; o >>= 1) { if (tid < o) red[tid] += red[tid + o]; __syncthreads(); }
    float mean = red[0] * (1.0f / DM);
    __syncthreads();
    float d0 = x0 - mean, d1 = x1 - mean, d2 = x2 - mean;
    red[tid] = d0 * d0 + d1 * d1 + d2 * d2;
    __syncthreads();
    for (int o = 128; o; o >>= 1) { if (tid < o) red[tid] += red[tid + o]; __syncthreads(); }
    float rs = rsqrtf(red[0] * (1.0f / DM) + 1e-6f);
    float* q = out + (long long)row * DM;
    q[tid]       = d0 * rs * g[tid]       + b[tid];
    q[tid + 256] = d1 * rs * g[tid + 256] + b[tid + 256];
    q[tid + 512] = d2 * rs * g[tid + 512] + b[tid + 512];
}

// ---------------- qkv reshape ----------------
__global__ void qkv_reshape_kernel(const float* __restrict__ qkv, float* __restrict__ qd,
                                   float* __restrict__ kd, float* __restrict__ vt) {
    long long idx = (long long)blockIdx.x * 256 + threadIdx.x;
    int tok = (int)(idx / DM), c = (int)(idx % DM);
    int h = c / DHD, d = c % DHD;
    int b = tok / NWRD, q = tok % NWRD;
    long long base = (long long)tok * G3;
    float qv = qkv[base + c];
    float kv = qkv[base + DM + c];
    float vv = qkv[base + 2 * DM + c];
    long long bh = b * NHEAD + h;
    qd[bh * NWRD * DHD + (long long)q * DHD + d] = qv;
    kd[bh * NWRD * DHD + (long long)q * DHD + d] = kv;
    vt[bh * DHD * NWRD + (long long)d * NWRD + q] = vv;
}

// ---------------- softmax (scale 1/sqrt(192)) ----------------
__global__ void softmax_kernel(float* __restrict__ s) {
    __shared__ float red[256];
    int row = blockIdx.x, tid = threadIdx.x;
    float* p = s + (long long)row * NWRD;
    float v = p[tid] * 0.07216878364870323f;
    red[tid] = v;
    __syncthreads();
    for (int o = 128; o; o >>= 1) { if (tid < o) red[tid] = fmaxf(red[tid], red[tid + o]); __syncthreads(); }
    float mx = red[0];
    __syncthreads();
    float e = expf(v - mx);
    red[tid] = e;
    __syncthreads();
    for (int o = 128; o; o >>= 1) { if (tid < o) red[tid] += red[tid + o]; __syncthreads(); }
    p[tid] = e / red[0];
}

// ---------------- attention out reshape ----------------
__global__ void o_reshape_kernel(const float* __restrict__ ob, float* __restrict__ oc) {
    long long idx = (long long)blockIdx.x * 256 + threadIdx.x;
    int tok = (int)(idx / DM), c = (int)(idx % DM);
    int h = c / DHD, d = c % DHD;
    int b = tok / NWRD, q = tok % NWRD;
    oc[idx] = ob[(((long long)(b * NHEAD + h)) * NWRD + q) * DHD + d];
}

// ---------------- launch ----------------
extern "C" void kernel_launch(void* const* d_in, const int* in_sizes, int n_in,
                              void* d_out, int out_size)
{
    const int*   x        = (const int*)  d_in[0];
    const float* bert_emb = (const float*)d_in[2];
    const float* emb      = (const float*)d_in[3];
    const float* wih0     = (const float*)d_in[4];
    const float* whh0     = (const float*)d_in[5];
    const float* bih0     = (const float*)d_in[6];
    const float* bhh0     = (const float*)d_in[7];
    const float* wih1     = (const float*)d_in[8];
    const float* whh1     = (const float*)d_in[9];
    const float* bih1     = (const float*)d_in[10];
    const float* bhh1     = (const float*)d_in[11];
    const float* wqkv     = (const float*)d_in[12];
    const float* bqkv     = (const float*)d_in[13];
    const float* wo       = (const float*)d_in[14];
    const float* bo       = (const float*)d_in[15];
    const float* w1       = (const float*)d_in[16];
    const float* b1       = (const float*)d_in[17];
    const float* w2       = (const float*)d_in[18];
    const float* b2       = (const float*)d_in[19];
    const float* ln1g     = (const float*)d_in[20];
    const float* ln1b     = (const float*)d_in[21];
    const float* ln2g     = (const float*)d_in[22];
    const float* ln2b     = (const float*)d_in[23];
    float* hout = (float*)d_out;

    float* arena;
    cudaGetSymbolAddress((void**)&arena, g_arena);
    float* gi  = arena + OFF_GI;
    float* y   = arena + OFF_Y;       // y0, then reused as y1
    float* seg = arena + OFF_SEGB;
    float* gh  = arena + OFF_GH;
    float* ha  = arena + OFF_HA;
    float* hb  = arena + OFF_HB;
    float* xn  = arena + OFF_SEGB + SB_XN;
    float* qkv = arena + OFF_SEGB + SB_QKV;
    float* q   = arena + OFF_SEGB + SB_Q;
    float* k   = arena + OFF_SEGB + SB_K;
    float* vt  = arena + OFF_SEGB + SB_VT;
    float* s   = arena + OFF_SEGB + SB_S;
    float* ob  = arena + OFF_SEGB + SB_OB;
    float* oc  = arena + OFF_SEGB + SB_OC;
    float* f1  = arena + OFF_SEGB + SB_F1;

    init_pow_kernel<<<1, DM>>>();
    embed_kernel<<<TOK, 256>>>(x, emb, seg);

    // gi layer 0: [dir][16384][2304] = seg @ wih0[dir]^T
    gemm_tc<0, 0><<<dim3(G3 / 128, TOK / 128, 2), 256>>>(
        seg, wih0, nullptr, gi, TOK, G3, DM, 0, (long long)G3 * DM, (long long)TOK * G3);

    // GRU layer 0 (writes y as y0)
    cudaMemsetAsync(ha, 0, (size_t)2 * BN * HH * sizeof(float));
    for (int st = 0; st < WLN; st++) {
        const float* hp = (st & 1) ? hb : ha;
        float*       hn = (st & 1) ? ha : hb;
        gemm_tc<0, 0><<<dim3(G3 / 128, BN / 128, 2), 256>>>(
            hp, whh0, nullptr, gh, BN, G3, HH,
            (long long)BN * HH, (long long)G3 * HH, (long long)BN * G3);
        gru_gate_kernel<<<(2 * BN * HH / 4) / 256, 256>>>(gi, gh, bih0, bhh0, hp, hn, y, st);
    }

    // gi layer 1 (reuses gi buffer): input = y0 concat [16384][1536]
    gemm_tc<0, 0><<<dim3(G3 / 128, TOK / 128, 2), 256>>>(
        y, wih1, nullptr, gi, TOK, G3, 2 * HH, 0, (long long)G3 * 2 * HH, (long long)TOK * G3);

    // GRU layer 1 (overwrites y as y1 — y0 is dead after the gi GEMM above)
    cudaMemsetAsync(ha, 0, (size_t)2 * BN * HH * sizeof(float));
    for (int st = 0; st < WLN; st++) {
        const float* hp = (st & 1) ? hb : ha;
        float*       hn = (st & 1) ? ha : hb;
        gemm_tc<0, 0><<<dim3(G3 / 128, BN / 128, 2), 256>>>(
            hp, whh1, nullptr, gh, BN, G3, HH,
            (long long)BN * HH, (long long)G3 * HH, (long long)BN * G3);
        gru_gate_kernel<<<(2 * BN * HH / 4) / 256, 256>>>(gi, gh, bih1, bhh1, hp, hn, y, st);
    }

    word_embed_kernel<<<BN, 256>>>(y, bert_emb, hout);

    for (int l = 0; l < 3; l++) {
        layernorm_kernel<<<BN, 256>>>(hout, ln1g + l * DM, ln1b + l * DM, xn);
        gemm_tc<0, 0><<<dim3(G3 / 128, BN / 128, 1), 256>>>(
            xn, wqkv + (long long)l * 3 * DM * DM, bqkv + l * 3 * DM, qkv, BN, G3, DM, 0, 0, 0);
        qkv_reshape_kernel<<<(BN * DM) / 256, 256>>>(qkv, q, k, vt);
        // S = Q @ K^T
        gemm_tc<0, 0><<<dim3(NWRD / 128, NWRD / 128, BB * NHEAD), 256>>>(
            q, k, nullptr, s, NWRD, NWRD, DHD,
            (long long)NWRD * DHD, (long long)NWRD * DHD, (long long)NWRD * NWRD);
        softmax_kernel<<<BB * NHEAD * NWRD, 256>>>(s);
        // O = S @ V   (N = 192 -> guarded)
        gemm_tc<0, 1><<<dim3(2, NWRD / 128, BB * NHEAD), 256>>>(
            s, vt, nullptr, ob, NWRD, DHD, NWRD,
            (long long)NWRD * NWRD, (long long)DHD * NWRD, (long long)NWRD * DHD);
        o_reshape_kernel<<<(BN * DM) / 256, 256>>>(ob, oc);
        gemm_tc<2, 0><<<dim3(DM / 128, BN / 128, 1), 256>>>(
            oc, wo + (long long)l * DM * DM, bo + l * DM, hout, BN, DM, DM, 0, 0, 0);
        layernorm_kernel<<<BN, 256>>>(hout, ln2g + l * DM, ln2b + l * DM, xn);
        gemm_tc<1, 0><<<dim3(FFD / 128, BN / 128, 1), 256>>>(
            xn, w1 + (long long)l * FFD * DM, b1 + l * FFD, f1, BN, FFD, DM, 0, 0, 0);
        gemm_tc<2, 0><<<dim3(DM / 128, BN / 128, 1), 256>>>(
            f1, w2 + (long long)l * DM * FFD, b2 + l * DM, hout, BN, DM, FFD, 0, 0, 0);
    }
}